// round 10
// baseline (speedup 1.0000x reference)
#include <cuda_runtime.h>
#include <math.h>
#include <stdint.h>

#define T_LEN 512
#define BATCH 64
#define ISZ   256
#define HID   512
#define GH    2048   // 4*HID, gate order f,i,o,c
#define NCTA  128

// ---------------- device scratch (no allocations allowed) ----------------
__device__ float g_gx[(size_t)T_LEN * GH * BATCH];  // [t][n=g*512+h][b] (bx+bh folded in)
__device__ float g_h[2][HID * BATCH];               // double-buffered h, [h][b]
__device__ unsigned g_flags[NCTA];                  // per-CTA step counters

// ---------------- packed f32x2 helpers (sm_100+) ----------------
union F2U { float2 f; unsigned long long u; };
__device__ __forceinline__ float2 ffma2(float2 a, float2 b, float2 c) {
    F2U A, B, C, D; A.f = a; B.f = b; C.f = c;
    asm("fma.rn.f32x2 %0, %1, %2, %3;" : "=l"(D.u) : "l"(A.u), "l"(B.u), "l"(C.u));
    return D.f;
}
__device__ __forceinline__ float2 fadd2(float2 a, float2 b) {
    F2U A, B, D; A.f = a; B.f = b;
    asm("add.rn.f32x2 %0, %1, %2;" : "=l"(D.u) : "l"(A.u), "l"(B.u));
    return D.f;
}
__device__ __forceinline__ float fast_sigmoid(float x) {
    return __fdividef(1.0f, 1.0f + __expf(-x));
}
__device__ __forceinline__ float fast_tanh(float x) {
    return __fdividef(2.0f, 1.0f + __expf(-2.0f * x)) - 1.0f;
}

// ---------------- release/acquire flag ops ----------------
__device__ __forceinline__ void flag_release(unsigned* p, unsigned v) {
    asm volatile("st.global.release.gpu.u32 [%0], %1;" :: "l"(p), "r"(v) : "memory");
}
__device__ __forceinline__ unsigned flag_acquire(const unsigned* p) {
    unsigned v;
    asm volatile("ld.global.acquire.gpu.u32 %0, [%1];" : "=r"(v) : "l"(p) : "memory");
    return v;
}

// ---------------- mbarrier helpers ----------------
__device__ __forceinline__ unsigned smem_u32(const void* p) {
    return (unsigned)__cvta_generic_to_shared(p);
}
__device__ __forceinline__ void mbar_init(unsigned bar, unsigned count) {
    asm volatile("mbarrier.init.shared.b64 [%0], %1;" :: "r"(bar), "r"(count) : "memory");
}
__device__ __forceinline__ void mbar_expect_tx(unsigned bar, unsigned bytes) {
    asm volatile("mbarrier.arrive.expect_tx.shared.b64 _, [%0], %1;"
                 :: "r"(bar), "r"(bytes) : "memory");
}
__device__ __forceinline__ void bulk_g2s(unsigned dst, const void* src, unsigned bytes, unsigned bar) {
    asm volatile("cp.async.bulk.shared::cta.global.mbarrier::complete_tx::bytes [%0], [%1], %2, [%3];"
                 :: "r"(dst), "l"(src), "r"(bytes), "r"(bar) : "memory");
}
__device__ __forceinline__ void mbar_wait(unsigned bar, unsigned parity) {
    asm volatile(
        "{\n\t"
        ".reg .pred P;\n\t"
        "WAIT_%=:\n\t"
        "mbarrier.try_wait.parity.acquire.cta.shared::cta.b64 P, [%0], %1;\n\t"
        "@!P bra WAIT_%=;\n\t"
        "}"
        :: "r"(bar), "r"(parity) : "memory");
}

// ---------------- init: zero h buffers + flags each replay ----------------
__global__ void init_state_kernel() {
    int idx = blockIdx.x * blockDim.x + threadIdx.x;
    if (idx < 2 * HID * BATCH) ((float*)g_h)[idx] = 0.0f;
    if (idx < NCTA) g_flags[idx] = 0u;
}

// ---------------- gx = x @ Wx^T + (bx + bh)  -> g_gx[t][n][b] ----------------
// CTA tile: 64 gate-rows x 64 batch, K=256. 256 threads, 8 warps.
// Warp w owns rows w*8..w*8+8 (split 4+4 by half-warp); lane = (rh, bp4).
// W staged row-major (uniform LDS.128); x staged k-major (LDS.128 = 2 f2 pairs).
// All MACs via fma.f32x2 (2 batches packed).
#define XS 68   // x_s row stride (floats), 16B-aligned
__global__ __launch_bounds__(256) void gx_kernel(const float* __restrict__ x,
                                                 const float* __restrict__ Wx,
                                                 const float* __restrict__ bx,
                                                 const float* __restrict__ bh) {
    extern __shared__ float sm[];
    float* Ws  = sm;                 // [64 r][256 k] row-major, 64 KB
    float* x_s = sm + 64 * 256;      // [256 k][XS] transposed, ~68 KB
    const int tid = threadIdx.x;
    const int t   = blockIdx.y;
    const int n0  = blockIdx.x * 64;

    // stage x[t] (b-major gmem) -> x_s[k][b]
    const float* xt = x + (size_t)t * BATCH * ISZ;
    #pragma unroll 4
    for (int it = 0; it < 64; it++) {
        int idx = it * 256 + tid;
        int b = idx >> 8;            // 0..63
        int i = idx & 255;
        x_s[i * XS + b] = xt[idx];
    }
    // stage W rows n0..n0+63 (contiguous)
    const float* Wrow = Wx + (size_t)n0 * ISZ;
    #pragma unroll 4
    for (int it = 0; it < 64; it++) {
        int idx = it * 256 + tid;
        Ws[idx] = Wrow[idx];
    }
    __syncthreads();

    const int lane = tid & 31;
    const int w    = tid >> 5;
    const int rh   = lane >> 4;          // 0..1
    const int bp4  = lane & 15;          // 0..15
    const int rb   = w * 8 + rh * 4;     // local row base (4 rows)
    const int b0   = bp4 * 4;            // batch base (4 batches)

    float2 a[4][2];
    #pragma unroll
    for (int r = 0; r < 4; r++) { a[r][0] = make_float2(0.f, 0.f); a[r][1] = a[r][0]; }

    const float4* W0 = (const float4*)(Ws + (rb + 0) * 256);
    const float4* W1 = (const float4*)(Ws + (rb + 1) * 256);
    const float4* W2 = (const float4*)(Ws + (rb + 2) * 256);
    const float4* W3 = (const float4*)(Ws + (rb + 3) * 256);

    #pragma unroll 2
    for (int k4 = 0; k4 < 64; k4++) {
        const float4 w0 = W0[k4];
        const float4 w1 = W1[k4];
        const float4 w2 = W2[k4];
        const float4 w3 = W3[k4];
        #pragma unroll
        for (int dk = 0; dk < 4; dk++) {
            const float4 xv = *(const float4*)(x_s + (k4 * 4 + dk) * XS + b0);
            const float2 hv0 = make_float2(xv.x, xv.y);
            const float2 hv1 = make_float2(xv.z, xv.w);
            const float s0 = dk == 0 ? w0.x : dk == 1 ? w0.y : dk == 2 ? w0.z : w0.w;
            const float s1 = dk == 0 ? w1.x : dk == 1 ? w1.y : dk == 2 ? w1.z : w1.w;
            const float s2 = dk == 0 ? w2.x : dk == 1 ? w2.y : dk == 2 ? w2.z : w2.w;
            const float s3 = dk == 0 ? w3.x : dk == 1 ? w3.y : dk == 2 ? w3.z : w3.w;
            const float2 d0 = make_float2(s0, s0);
            const float2 d1 = make_float2(s1, s1);
            const float2 d2 = make_float2(s2, s2);
            const float2 d3 = make_float2(s3, s3);
            a[0][0] = ffma2(hv0, d0, a[0][0]); a[0][1] = ffma2(hv1, d0, a[0][1]);
            a[1][0] = ffma2(hv0, d1, a[1][0]); a[1][1] = ffma2(hv1, d1, a[1][1]);
            a[2][0] = ffma2(hv0, d2, a[2][0]); a[2][1] = ffma2(hv1, d2, a[2][1]);
            a[3][0] = ffma2(hv0, d3, a[3][0]); a[3][1] = ffma2(hv1, d3, a[3][1]);
        }
    }

    #pragma unroll
    for (int r = 0; r < 4; r++) {
        const int n = n0 + rb + r;
        const float bias = __ldg(&bx[n]) + __ldg(&bh[n]);
        float4 out = make_float4(a[r][0].x + bias, a[r][0].y + bias,
                                 a[r][1].x + bias, a[r][1].y + bias);
        *(float4*)&g_gx[((size_t)t * GH + n) * BATCH + b0] = out;
    }
}

// ---------------- persistent recurrence kernel ----------------
// 128 CTAs (1/SM) x 512 threads (16 warps). CTA owns 4 hidden units (16 rows).
// h-quarter q produced by CTAs bid in [32q, 32q+32): per-CTA flags, no atomics.
// Warp w: ke = w>>1 (k-eighth, 64 k), hlh = w&1 (hl pair). Lane = batch pair.
// Stager warps 0/5/10/15 poll their quarter's 32 flags lane-parallel, then
// bulk-copy 32 KB. Release = st.release.gpu of this CTA's flag.
__global__ __launch_bounds__(512, 1) void lstm_persistent(
        const float* __restrict__ Wh,
        float* __restrict__ h_seq,
        float* __restrict__ out_hlast,
        float* __restrict__ out_clast) {
    extern __shared__ float sm[];
    float*  Wsp  = sm;                      // [512 k][16 r(hl,g)]  32 KB
    float*  hs   = sm + 8192;               // [512 k][64 b]       128 KB
    float2* red  = (float2*)(sm + 8192 + 32768);  // [8 ke][4 hl][2 gp][64 b] 32 KB
    unsigned long long* mbar = (unsigned long long*)(sm + 8192 + 32768 + 8192);

    const int tid  = threadIdx.x;
    const int lane = tid & 31;
    const int warp = tid >> 5;
    const int bp   = lane;
    const int hlh  = warp & 1;
    const int ke   = warp >> 1;              // k-eighth 0..7
    const int khq  = ke >> 1;                // k-quarter 0..3 (mbar index)
    const int bid  = blockIdx.x;
    const int h0   = bid * 4;
    const bool is_stager = ((warp % 5) == 0);    // warps 0,5,10,15
    const int  sq = warp / 5;                    // staged quarter == own khq

    // ---- stage Wsp once: Wsp[k*16 + hl*4 + g] = Wh[g*512 + h0 + hl][k]
    #pragma unroll
    for (int it = 0; it < 16; it++) {
        int idx = it * 512 + tid;            // 0..8191 = r*512 + k
        int r = idx >> 9, k = idx & 511;
        int hl = r >> 2, g = r & 3;
        Wsp[k * 16 + hl * 4 + g] = Wh[((size_t)(g * HID + h0 + hl)) * HID + k];
    }
    if (tid == 0) {
        #pragma unroll
        for (int q = 0; q < 4; q++) mbar_init(smem_u32(&mbar[q]), 1);
    }

    // epilogue threads: tid < 128 -> cell (ehl = tid>>5, ebp = tid&31)
    const bool epi = (tid < 128);
    const int ehl = tid >> 5;
    const int ebp = tid & 31;
    const int eh  = h0 + ehl;
    float c0 = 0.0f, c1 = 0.0f;

    const unsigned my_bar  = smem_u32(&mbar[khq]);
    const unsigned hs_dst0 = smem_u32(hs);
    const unsigned* poll_flag = &g_flags[sq * 32 + lane];  // valid for stagers

    __syncthreads();

    int cur = 0;
    for (int t = 0; t < T_LEN; t++) {
        // ---- gx prefetch (h-independent; overlaps the flag poll)
        float2 gxf, gxi, gxo, gxc;
        if (epi) {
            const float* gp = g_gx + ((size_t)t * GH + eh) * BATCH + 2 * ebp;
            gxf = __ldg((const float2*)(gp + (size_t)0 * HID * BATCH));
            gxi = __ldg((const float2*)(gp + (size_t)1 * HID * BATCH));
            gxo = __ldg((const float2*)(gp + (size_t)2 * HID * BATCH));
            gxc = __ldg((const float2*)(gp + (size_t)3 * HID * BATCH));
        }

        // ---- stager warp: lane-parallel poll of 32 producer flags, then copy
        if (is_stager) {
            if (t > 0) {
                while (flag_acquire(poll_flag) < (unsigned)t) { __nanosleep(32); }
            }
            __syncwarp();
            if (lane == 0) {
                mbar_expect_tx(my_bar, 32768u);
                bulk_g2s(hs_dst0 + (unsigned)sq * 32768u,
                         (const char*)g_h[cur] + (unsigned)sq * 32768u,
                         32768u, my_bar);
            }
        }

        // ---- wait only for this warp's k-quarter
        mbar_wait(my_bar, (unsigned)(t & 1));

        // ---- compute: 64 k x (2 hl rows x 2 gate-pairs x 2 batches)
        float2 A000 = make_float2(0.f, 0.f), A001 = A000, A010 = A000, A011 = A000;
        float2 A100 = A000, A101 = A000, A110 = A000, A111 = A000;

        const float* wP = Wsp + (ke * 64) * 16 + 8 * hlh;
        const float* hP = hs + (ke * 64) * 64 + 2 * bp;

        #pragma unroll 8
        for (int kl = 0; kl < 64; kl++) {
            const float4 w4a = *(const float4*)(wP);       // rows: hl=2hlh, gates 0..3
            const float4 w4b = *(const float4*)(wP + 4);   // rows: hl=2hlh+1
            const float2 hv  = *(const float2*)(hP);
            const float2 d0 = make_float2(hv.x, hv.x);
            const float2 d1 = make_float2(hv.y, hv.y);
            const float2 w01a = make_float2(w4a.x, w4a.y);
            const float2 w23a = make_float2(w4a.z, w4a.w);
            const float2 w01b = make_float2(w4b.x, w4b.y);
            const float2 w23b = make_float2(w4b.z, w4b.w);
            A000 = ffma2(w01a, d0, A000);
            A001 = ffma2(w01a, d1, A001);
            A010 = ffma2(w23a, d0, A010);
            A011 = ffma2(w23a, d1, A011);
            A100 = ffma2(w01b, d0, A100);
            A101 = ffma2(w01b, d1, A101);
            A110 = ffma2(w23b, d0, A110);
            A111 = ffma2(w23b, d1, A111);
            wP += 16;
            hP += 64;
        }

        // ---- guard: previous step's red consumers must be done (skip at t=0)
        if (t > 0 && !epi) {
            asm volatile("bar.sync 2, 512;" ::: "memory");
        }

        // ---- scatter partials: red[((ke*4+hl)*2+gp)*64 + b] (f2 = gate pair)
        {
            const int hlA = 2 * hlh, hlB = 2 * hlh + 1;
            float4* r0 = (float4*)(red + ((ke * 4 + hlA) * 2 + 0) * 64 + 2 * bp);
            float4* r1 = (float4*)(red + ((ke * 4 + hlA) * 2 + 1) * 64 + 2 * bp);
            float4* r2 = (float4*)(red + ((ke * 4 + hlB) * 2 + 0) * 64 + 2 * bp);
            float4* r3 = (float4*)(red + ((ke * 4 + hlB) * 2 + 1) * 64 + 2 * bp);
            *r0 = make_float4(A000.x, A000.y, A001.x, A001.y);
            *r1 = make_float4(A010.x, A010.y, A011.x, A011.y);
            *r2 = make_float4(A100.x, A100.y, A101.x, A101.y);
            *r3 = make_float4(A110.x, A110.y, A111.x, A111.y);
        }
        __syncthreads();

        // ---- reduce 8 k-eighths + gates + publish (epi threads only)
        if (epi) {
            float2 s01_0 = make_float2(0.f, 0.f), s01_1 = s01_0;
            float2 s23_0 = s01_0, s23_1 = s01_0;
            #pragma unroll
            for (int q = 0; q < 8; q++) {
                const float4 v01 = *(const float4*)(red + ((q * 4 + ehl) * 2 + 0) * 64 + 2 * ebp);
                const float4 v23 = *(const float4*)(red + ((q * 4 + ehl) * 2 + 1) * 64 + 2 * ebp);
                s01_0 = fadd2(s01_0, make_float2(v01.x, v01.y));
                s01_1 = fadd2(s01_1, make_float2(v01.z, v01.w));
                s23_0 = fadd2(s23_0, make_float2(v23.x, v23.y));
                s23_1 = fadd2(s23_1, make_float2(v23.z, v23.w));
            }
            // s01 = (f, i), s23 = (o, c); gx already contains bx + bh
            const float pf0 = s01_0.x + gxf.x, pf1 = s01_1.x + gxf.y;
            const float pi0 = s01_0.y + gxi.x, pi1 = s01_1.y + gxi.y;
            const float po0 = s23_0.x + gxo.x, po1 = s23_1.x + gxo.y;
            const float pc0 = s23_0.y + gxc.x, pc1 = s23_1.y + gxc.y;

            const float f0 = fast_sigmoid(pf0), f1 = fast_sigmoid(pf1);
            const float i0 = fast_sigmoid(pi0), i1 = fast_sigmoid(pi1);
            const float o0 = fast_sigmoid(po0), o1 = fast_sigmoid(po1);
            const float q0 = fast_tanh(pc0),    q1 = fast_tanh(pc1);

            c0 = f0 * c0 + i0 * q0;
            c1 = f1 * c1 + i1 * q1;
            const float hn0 = o0 * fast_tanh(c0);
            const float hn1 = o1 * fast_tanh(c1);

            // publish next-step h first (only thing other CTAs wait on)
            __stcg((float2*)(g_h[cur ^ 1] + eh * BATCH + 2 * ebp),
                   make_float2(hn0, hn1));

            // red fully consumed -> release barrier 2
            asm volatile("bar.arrive 2, 512;" ::: "memory");

            // epi-only named barrier (h stores done), then release this CTA's flag
            asm volatile("bar.sync 1, 128;" ::: "memory");
            if (tid == 0) {
                flag_release(&g_flags[bid], (unsigned)(t + 1));
            }

            // off-critical-path outputs
            float* so = h_seq + ((size_t)t * BATCH + 2 * ebp) * HID + eh;
            so[0]   = hn0;
            so[HID] = hn1;
            if (t == T_LEN - 1) {
                out_hlast[(size_t)(2 * ebp) * HID + eh]     = hn0;
                out_hlast[(size_t)(2 * ebp + 1) * HID + eh] = hn1;
                out_clast[(size_t)(2 * ebp) * HID + eh]     = c0;
                out_clast[(size_t)(2 * ebp + 1) * HID + eh] = c1;
            }
        }

        cur ^= 1;
    }
}

// ---------------- launch ----------------
extern "C" void kernel_launch(void* const* d_in, const int* in_sizes, int n_in,
                              void* d_out, int out_size) {
    const float* x  = (const float*)d_in[0];
    const float* Wx = (const float*)d_in[1];
    const float* bx = (const float*)d_in[2];
    const float* Wh = (const float*)d_in[3];
    const float* bh = (const float*)d_in[4];

    float* out       = (float*)d_out;
    float* out_hlast = out + (size_t)T_LEN * BATCH * HID;
    float* out_clast = out_hlast + (size_t)BATCH * HID;

    const int gx_smem = (64 * 256 + 256 * XS) * sizeof(float);      // 135168 B
    const int ps_smem = (8192 + 32768 + 8192) * sizeof(float) + 64; // 196672 B
    cudaFuncSetAttribute(gx_kernel,       cudaFuncAttributeMaxDynamicSharedMemorySize, gx_smem);
    cudaFuncSetAttribute(lstm_persistent, cudaFuncAttributeMaxDynamicSharedMemorySize, ps_smem);

    init_state_kernel<<<128, 512>>>();
    gx_kernel<<<dim3(32, 512), 256, gx_smem>>>(x, Wx, bx, bh);
    lstm_persistent<<<NCTA, 512, ps_smem>>>(Wh, out, out_hlast, out_clast);
}

// round 11
// speedup vs baseline: 1.1279x; 1.1279x over previous
#include <cuda_runtime.h>
#include <math.h>
#include <stdint.h>

#define T_LEN 512
#define BATCH 64
#define ISZ   256
#define HID   512
#define GH    2048   // 4*HID, gate order f,i,o,c
#define NCTA  128

// ---------------- device scratch (no allocations allowed) ----------------
__device__ float g_gx[(size_t)T_LEN * GH * BATCH];  // [t][n=g*512+h][b] (bx+bh folded in)
__device__ float g_h[2][HID * BATCH];               // double-buffered h, [h][b]
__device__ unsigned g_bars[4];                      // per-group arrival counters
__device__ volatile unsigned g_epochs[4];           // per-group release epochs

// ---------------- packed f32x2 helpers (sm_100+) ----------------
union F2U { float2 f; unsigned long long u; };
__device__ __forceinline__ float2 ffma2(float2 a, float2 b, float2 c) {
    F2U A, B, C, D; A.f = a; B.f = b; C.f = c;
    asm("fma.rn.f32x2 %0, %1, %2, %3;" : "=l"(D.u) : "l"(A.u), "l"(B.u), "l"(C.u));
    return D.f;
}
__device__ __forceinline__ float2 fadd2(float2 a, float2 b) {
    F2U A, B, D; A.f = a; B.f = b;
    asm("add.rn.f32x2 %0, %1, %2;" : "=l"(D.u) : "l"(A.u), "l"(B.u));
    return D.f;
}
__device__ __forceinline__ float fast_sigmoid(float x) {
    return __fdividef(1.0f, 1.0f + __expf(-x));
}
__device__ __forceinline__ float fast_tanh(float x) {
    return __fdividef(2.0f, 1.0f + __expf(-2.0f * x)) - 1.0f;
}

// ---------------- mbarrier helpers ----------------
__device__ __forceinline__ unsigned smem_u32(const void* p) {
    return (unsigned)__cvta_generic_to_shared(p);
}
__device__ __forceinline__ void mbar_init(unsigned bar, unsigned count) {
    asm volatile("mbarrier.init.shared.b64 [%0], %1;" :: "r"(bar), "r"(count) : "memory");
}
__device__ __forceinline__ void mbar_expect_tx(unsigned bar, unsigned bytes) {
    asm volatile("mbarrier.arrive.expect_tx.shared.b64 _, [%0], %1;"
                 :: "r"(bar), "r"(bytes) : "memory");
}
__device__ __forceinline__ void bulk_g2s(unsigned dst, const void* src, unsigned bytes, unsigned bar) {
    asm volatile("cp.async.bulk.shared::cta.global.mbarrier::complete_tx::bytes [%0], [%1], %2, [%3];"
                 :: "r"(dst), "l"(src), "r"(bytes), "r"(bar) : "memory");
}
__device__ __forceinline__ void mbar_wait(unsigned bar, unsigned parity) {
    asm volatile(
        "{\n\t"
        ".reg .pred P;\n\t"
        "WAIT_%=:\n\t"
        "mbarrier.try_wait.parity.acquire.cta.shared::cta.b64 P, [%0], %1;\n\t"
        "@!P bra WAIT_%=;\n\t"
        "}"
        :: "r"(bar), "r"(parity) : "memory");
}

// ---------------- init: zero h buffers + barrier state ----------------
__global__ void init_state_kernel() {
    int idx = blockIdx.x * blockDim.x + threadIdx.x;
    if (idx < 2 * HID * BATCH) ((float*)g_h)[idx] = 0.0f;
    if (idx < 4) { g_bars[idx] = 0; g_epochs[idx] = 0; }
}

// ---------------- gx = x @ Wx^T + (bx + bh)  -> g_gx[t][n][b] ----------------
// CTA: 128 threads, tile 32 gate-rows x 64 batch, K=256 (2 CTAs/SM).
// Wt smem transposed [k][r] (stride 36, f4-aligned): LDS.128 yields natural
// row-pair float2s. Accumulator = row-pair; x duplicated (2 MOV/k), reused
// across 4 row-pairs. Warp = 16-batch block; lane = (rt 0..3, bp 0..7).
// Per thread per k: 2 LDS.128 + 1 LDS.64 + 2 dup + 8 FFMA2 -> FMA-pipe-bound.
#define XS  66   // x_s row stride (even -> f2 aligned)
#define WTS 36   // Wt row stride (mult of 4 -> f4 aligned)
__global__ __launch_bounds__(128) void gx_kernel(const float* __restrict__ x,
                                                 const float* __restrict__ Wx,
                                                 const float* __restrict__ bx,
                                                 const float* __restrict__ bh) {
    extern __shared__ float sm[];
    float* x_s = sm;                 // [256 k][XS]
    float* Wt  = sm + 256 * XS;      // [256 k][WTS] rows 0..31 transposed
    const int tid = threadIdx.x;
    const int t   = blockIdx.y;
    const int n0  = blockIdx.x * 32;

    // stage x[t] (b-major gmem) -> x_s[k][b]
    const float* xt = x + (size_t)t * BATCH * ISZ;
    #pragma unroll 4
    for (int it = 0; it < 128; it++) {
        int idx = it * 128 + tid;
        int b = idx >> 8;            // 0..63
        int i = idx & 255;
        x_s[i * XS + b] = xt[idx];
    }
    // stage W transposed: coalesced gmem read, strided smem write
    const float* Wrow = Wx + (size_t)n0 * ISZ;
    #pragma unroll 4
    for (int it = 0; it < 64; it++) {
        int idx = it * 128 + tid;    // 0..8191 = r*256 + k
        int r = idx >> 8;
        int k = idx & 255;
        Wt[k * WTS + r] = Wrow[idx];
    }
    __syncthreads();

    const int lane = tid & 31;
    const int warp = tid >> 5;           // batch 16-block
    const int rt   = lane >> 3;          // 0..3 -> rows rt*8..rt*8+7
    const int bp   = lane & 7;
    const int b0   = warp * 16 + 2 * bp; // 2 batches
    const int rbase = rt * 8;

    float2 A[4][2];                      // [row-pair][batch]
    #pragma unroll
    for (int rp = 0; rp < 4; rp++) { A[rp][0] = make_float2(0.f, 0.f); A[rp][1] = A[rp][0]; }

    const float* wbase = Wt + rbase;
    const float* xbase = x_s + b0;

    #pragma unroll 4
    for (int k = 0; k < 256; k++) {
        const float4 wv0 = *(const float4*)(wbase + k * WTS);      // rows rbase+0..3
        const float4 wv1 = *(const float4*)(wbase + k * WTS + 4);  // rows rbase+4..7
        const float2 xv  = *(const float2*)(xbase + k * XS);
        const float2 d0 = make_float2(xv.x, xv.x);
        const float2 d1 = make_float2(xv.y, xv.y);
        const float2 p0 = make_float2(wv0.x, wv0.y);
        const float2 p1 = make_float2(wv0.z, wv0.w);
        const float2 p2 = make_float2(wv1.x, wv1.y);
        const float2 p3 = make_float2(wv1.z, wv1.w);
        A[0][0] = ffma2(p0, d0, A[0][0]);  A[0][1] = ffma2(p0, d1, A[0][1]);
        A[1][0] = ffma2(p1, d0, A[1][0]);  A[1][1] = ffma2(p1, d1, A[1][1]);
        A[2][0] = ffma2(p2, d0, A[2][0]);  A[2][1] = ffma2(p2, d1, A[2][1]);
        A[3][0] = ffma2(p3, d0, A[3][0]);  A[3][1] = ffma2(p3, d1, A[3][1]);
    }

    // epilogue: A[rp][bt] = (row rbase+2rp, row rbase+2rp+1) for batch b0+bt
    #pragma unroll
    for (int rp = 0; rp < 4; rp++) {
        const int r0 = n0 + rbase + 2 * rp;
        const float bias0 = __ldg(&bx[r0]) + __ldg(&bh[r0]);
        const float bias1 = __ldg(&bx[r0 + 1]) + __ldg(&bh[r0 + 1]);
        float* o0 = &g_gx[((size_t)t * GH + r0) * BATCH + b0];
        float* o1 = o0 + BATCH;
        o0[0] = A[rp][0].x + bias0;
        o0[1] = A[rp][1].x + bias0;
        o1[0] = A[rp][0].y + bias1;
        o1[1] = A[rp][1].y + bias1;
    }
}

// ---------------- persistent recurrence kernel (R8, unchanged) ----------------
// 128 CTAs (1/SM) x 512 threads (16 warps). CTA owns 4 hidden units (16 rows).
// h-quarter q produced by CTA group q (bid in [32q, 32q+32)) -> g_epochs[q].
// Warp w: ke = w>>1 (k-eighth, 64 k), hlh = w&1 (hl pair). Lane = batch pair.
// Stager warps 0/5/10/15 (one per SMSP) stage quarter w/5 via cp.async.bulk.
// red race guarded by named barrier 2 (epi arrives after consuming red).
__global__ __launch_bounds__(512, 1) void lstm_persistent(
        const float* __restrict__ Wh,
        float* __restrict__ h_seq,
        float* __restrict__ out_hlast,
        float* __restrict__ out_clast) {
    extern __shared__ float sm[];
    float*  Wsp  = sm;                      // [512 k][16 r(hl,g)]  32 KB
    float*  hs   = sm + 8192;               // [512 k][64 b]       128 KB
    float2* red  = (float2*)(sm + 8192 + 32768);  // [8 ke][4 hl][2 gp][64 b] 32 KB
    unsigned long long* mbar = (unsigned long long*)(sm + 8192 + 32768 + 8192);

    const int tid  = threadIdx.x;
    const int lane = tid & 31;
    const int warp = tid >> 5;
    const int bp   = lane;
    const int hlh  = warp & 1;
    const int ke   = warp >> 1;              // k-eighth 0..7
    const int khq  = ke >> 1;                // k-quarter 0..3 (mbar index)
    const int bid  = blockIdx.x;
    const int h0   = bid * 4;
    const int gid  = bid >> 5;               // this CTA's producer group
    const bool is_stager = ((warp % 5) == 0);    // warps 0,5,10,15
    const int  sq = warp / 5;                    // staged quarter (valid for stagers)

    // ---- stage Wsp once: Wsp[k*16 + hl*4 + g] = Wh[g*512 + h0 + hl][k]
    #pragma unroll
    for (int it = 0; it < 16; it++) {
        int idx = it * 512 + tid;            // 0..8191 = r*512 + k
        int r = idx >> 9, k = idx & 511;
        int hl = r >> 2, g = r & 3;
        Wsp[k * 16 + hl * 4 + g] = Wh[((size_t)(g * HID + h0 + hl)) * HID + k];
    }
    if (tid == 0) {
        #pragma unroll
        for (int q = 0; q < 4; q++) mbar_init(smem_u32(&mbar[q]), 1);
    }

    // epilogue threads: tid < 128 -> cell (ehl = tid>>5, ebp = tid&31)
    const bool epi = (tid < 128);
    const int ehl = tid >> 5;
    const int ebp = tid & 31;
    const int eh  = h0 + ehl;
    float c0 = 0.0f, c1 = 0.0f;

    const unsigned my_bar  = smem_u32(&mbar[khq]);
    const unsigned hs_dst0 = smem_u32(hs);

    __syncthreads();

    int cur = 0;
    for (int t = 0; t < T_LEN; t++) {
        // ---- gx prefetch (h-independent; overlaps the epoch wait)
        float2 gxf, gxi, gxo, gxc;
        if (epi) {
            const float* gp = g_gx + ((size_t)t * GH + eh) * BATCH + 2 * ebp;
            gxf = __ldg((const float2*)(gp + (size_t)0 * HID * BATCH));
            gxi = __ldg((const float2*)(gp + (size_t)1 * HID * BATCH));
            gxo = __ldg((const float2*)(gp + (size_t)2 * HID * BATCH));
            gxc = __ldg((const float2*)(gp + (size_t)3 * HID * BATCH));
        }

        // ---- per-quarter stager: wait for its producer group, then copy 32 KB
        if (is_stager && lane == 0) {
            if (t > 0) {
                while (g_epochs[sq] < (unsigned)t) { __nanosleep(32); }
            }
            mbar_expect_tx(smem_u32(&mbar[sq]), 32768u);
            bulk_g2s(hs_dst0 + (unsigned)sq * 32768u,
                     (const char*)g_h[cur] + (unsigned)sq * 32768u,
                     32768u, smem_u32(&mbar[sq]));
        }

        // ---- wait only for this warp's k-quarter
        mbar_wait(my_bar, (unsigned)(t & 1));

        // ---- compute: 64 k x (2 hl rows x 2 gate-pairs x 2 batches)
        float2 A000 = make_float2(0.f, 0.f), A001 = A000, A010 = A000, A011 = A000;
        float2 A100 = A000, A101 = A000, A110 = A000, A111 = A000;

        const float* wP = Wsp + (ke * 64) * 16 + 8 * hlh;
        const float* hP = hs + (ke * 64) * 64 + 2 * bp;

        #pragma unroll 8
        for (int kl = 0; kl < 64; kl++) {
            const float4 w4a = *(const float4*)(wP);       // rows: hl=2hlh, gates 0..3
            const float4 w4b = *(const float4*)(wP + 4);   // rows: hl=2hlh+1
            const float2 hv  = *(const float2*)(hP);
            const float2 d0 = make_float2(hv.x, hv.x);
            const float2 d1 = make_float2(hv.y, hv.y);
            const float2 w01a = make_float2(w4a.x, w4a.y);
            const float2 w23a = make_float2(w4a.z, w4a.w);
            const float2 w01b = make_float2(w4b.x, w4b.y);
            const float2 w23b = make_float2(w4b.z, w4b.w);
            A000 = ffma2(w01a, d0, A000);
            A001 = ffma2(w01a, d1, A001);
            A010 = ffma2(w23a, d0, A010);
            A011 = ffma2(w23a, d1, A011);
            A100 = ffma2(w01b, d0, A100);
            A101 = ffma2(w01b, d1, A101);
            A110 = ffma2(w23b, d0, A110);
            A111 = ffma2(w23b, d1, A111);
            wP += 16;
            hP += 64;
        }

        // ---- guard: previous step's red consumers must be done (skip at t=0)
        if (t > 0 && !epi) {
            asm volatile("bar.sync 2, 512;" ::: "memory");
        }

        // ---- scatter partials: red[((ke*4+hl)*2+gp)*64 + b] (f2 = gate pair)
        {
            const int hlA = 2 * hlh, hlB = 2 * hlh + 1;
            float4* r0 = (float4*)(red + ((ke * 4 + hlA) * 2 + 0) * 64 + 2 * bp);
            float4* r1 = (float4*)(red + ((ke * 4 + hlA) * 2 + 1) * 64 + 2 * bp);
            float4* r2 = (float4*)(red + ((ke * 4 + hlB) * 2 + 0) * 64 + 2 * bp);
            float4* r3 = (float4*)(red + ((ke * 4 + hlB) * 2 + 1) * 64 + 2 * bp);
            *r0 = make_float4(A000.x, A000.y, A001.x, A001.y);
            *r1 = make_float4(A010.x, A010.y, A011.x, A011.y);
            *r2 = make_float4(A100.x, A100.y, A101.x, A101.y);
            *r3 = make_float4(A110.x, A110.y, A111.x, A111.y);
        }
        __syncthreads();

        // ---- reduce 8 k-eighths + gates + publish (epi threads only)
        if (epi) {
            float2 s01_0 = make_float2(0.f, 0.f), s01_1 = s01_0;
            float2 s23_0 = s01_0, s23_1 = s01_0;
            #pragma unroll
            for (int q = 0; q < 8; q++) {
                const float4 v01 = *(const float4*)(red + ((q * 4 + ehl) * 2 + 0) * 64 + 2 * ebp);
                const float4 v23 = *(const float4*)(red + ((q * 4 + ehl) * 2 + 1) * 64 + 2 * ebp);
                s01_0 = fadd2(s01_0, make_float2(v01.x, v01.y));
                s01_1 = fadd2(s01_1, make_float2(v01.z, v01.w));
                s23_0 = fadd2(s23_0, make_float2(v23.x, v23.y));
                s23_1 = fadd2(s23_1, make_float2(v23.z, v23.w));
            }
            // s01 = (f, i), s23 = (o, c); gx already contains bx + bh
            const float pf0 = s01_0.x + gxf.x, pf1 = s01_1.x + gxf.y;
            const float pi0 = s01_0.y + gxi.x, pi1 = s01_1.y + gxi.y;
            const float po0 = s23_0.x + gxo.x, po1 = s23_1.x + gxo.y;
            const float pc0 = s23_0.y + gxc.x, pc1 = s23_1.y + gxc.y;

            const float f0 = fast_sigmoid(pf0), f1 = fast_sigmoid(pf1);
            const float i0 = fast_sigmoid(pi0), i1 = fast_sigmoid(pi1);
            const float o0 = fast_sigmoid(po0), o1 = fast_sigmoid(po1);
            const float q0 = fast_tanh(pc0),    q1 = fast_tanh(pc1);

            c0 = f0 * c0 + i0 * q0;
            c1 = f1 * c1 + i1 * q1;
            const float hn0 = o0 * fast_tanh(c0);
            const float hn1 = o1 * fast_tanh(c1);

            // publish next-step h first (only thing other CTAs wait on)
            __stcg((float2*)(g_h[cur ^ 1] + eh * BATCH + 2 * ebp),
                   make_float2(hn0, hn1));

            // red fully consumed (values folded into hn/c) -> release barrier 2
            asm volatile("bar.arrive 2, 512;" ::: "memory");

            // epi-only named barrier (warps 0-3, 128 threads), then release
            asm volatile("bar.sync 1, 128;" ::: "memory");
            if (tid == 0) {
                __threadfence();
                unsigned old = atomicAdd(&g_bars[gid], 1u);
                if (old == (unsigned)t * 32u + 31u) {
                    g_epochs[gid] = (unsigned)(t + 1);
                }
            }

            // off-critical-path outputs
            float* so = h_seq + ((size_t)t * BATCH + 2 * ebp) * HID + eh;
            so[0]   = hn0;
            so[HID] = hn1;
            if (t == T_LEN - 1) {
                out_hlast[(size_t)(2 * ebp) * HID + eh]     = hn0;
                out_hlast[(size_t)(2 * ebp + 1) * HID + eh] = hn1;
                out_clast[(size_t)(2 * ebp) * HID + eh]     = c0;
                out_clast[(size_t)(2 * ebp + 1) * HID + eh] = c1;
            }
        }

        cur ^= 1;
    }
}

// ---------------- launch ----------------
extern "C" void kernel_launch(void* const* d_in, const int* in_sizes, int n_in,
                              void* d_out, int out_size) {
    const float* x  = (const float*)d_in[0];
    const float* Wx = (const float*)d_in[1];
    const float* bx = (const float*)d_in[2];
    const float* Wh = (const float*)d_in[3];
    const float* bh = (const float*)d_in[4];

    float* out       = (float*)d_out;
    float* out_hlast = out + (size_t)T_LEN * BATCH * HID;
    float* out_clast = out_hlast + (size_t)BATCH * HID;

    const int gx_smem = (256 * XS + 256 * WTS) * sizeof(float);     // 104448 B
    const int ps_smem = (8192 + 32768 + 8192) * sizeof(float) + 64; // 196672 B
    cudaFuncSetAttribute(gx_kernel,       cudaFuncAttributeMaxDynamicSharedMemorySize, gx_smem);
    cudaFuncSetAttribute(lstm_persistent, cudaFuncAttributeMaxDynamicSharedMemorySize, ps_smem);

    init_state_kernel<<<128, 512>>>();
    gx_kernel<<<dim3(64, 512), 128, gx_smem>>>(x, Wx, bx, bh);
    lstm_persistent<<<NCTA, 512, ps_smem>>>(Wh, out, out_hlast, out_clast);
}